// round 16
// baseline (speedup 1.0000x reference)
#include <cuda_runtime.h>
#include <cuda_fp16.h>
#include <math.h>
#include <cstdint>

// Problem constants
constexpr int Bn = 4;
constexpr int Sn = 2048;
constexpr int Dn = 1024;
constexpr int Hn = 16;
constexpr int DKn = 64;
constexpr int Mn = Bn * Sn;  // 8192

// Q pre-scale: 1/sqrt(64) * log2(e)
#define QSCALE 0.18033688011112042f
// Masked-score value (row max >= 0 via diagonal self-logit)
#define MASKV -64.0f

// ---------------------------------------------------------------------------
// Scratch (static device arrays — no allocation allowed)
// ---------------------------------------------------------------------------
__device__ __half g_xf[Mn * Dn];
__device__ __half g_Wh[4 * Dn * Dn];
__device__ __half g_Q[Mn * Dn];
__device__ __half g_K[Mn * Dn];
__device__ __half g_V[Mn * Dn];
__device__ __half g_ah[Mn * Dn];
__device__ float g_cos[Sn * 32];
__device__ float g_sin[Sn * 32];

// ---------------------------------------------------------------------------
// PTX helpers
// ---------------------------------------------------------------------------
__device__ __forceinline__ uint32_t s2u(const void* p) {
    uint32_t a;
    asm("{ .reg .u64 t; cvta.to.shared.u64 t, %1; cvt.u32.u64 %0, t; }"
        : "=r"(a) : "l"(p));
    return a;
}

__device__ __forceinline__ void cpa16(uint32_t dst, const void* src) {
    asm volatile("cp.async.cg.shared.global [%0], [%1], 16;"
                 :: "r"(dst), "l"(src) : "memory");
}
#define CP_COMMIT() asm volatile("cp.async.commit_group;" ::: "memory")
#define CP_WAIT1() asm volatile("cp.async.wait_group 1;" ::: "memory")
#define CP_WAIT0() asm volatile("cp.async.wait_group 0;" ::: "memory")

__device__ __forceinline__ void ldsm4(uint32_t addr, uint32_t* r) {
    asm volatile(
        "ldmatrix.sync.aligned.m8n8.x4.shared.b16 {%0,%1,%2,%3}, [%4];"
        : "=r"(r[0]), "=r"(r[1]), "=r"(r[2]), "=r"(r[3]) : "r"(addr));
}

__device__ __forceinline__ void ldsm4t(uint32_t addr, uint32_t* r) {
    asm volatile(
        "ldmatrix.sync.aligned.m8n8.x4.trans.shared.b16 {%0,%1,%2,%3}, [%4];"
        : "=r"(r[0]), "=r"(r[1]), "=r"(r[2]), "=r"(r[3]) : "r"(addr));
}

__device__ __forceinline__ void mma_f16(float* c, const uint32_t* a,
                                        uint32_t b0, uint32_t b1) {
    asm volatile(
        "mma.sync.aligned.m16n8k16.row.col.f32.f16.f16.f32 "
        "{%0,%1,%2,%3}, {%4,%5,%6,%7}, {%8,%9}, {%0,%1,%2,%3};"
        : "+f"(c[0]), "+f"(c[1]), "+f"(c[2]), "+f"(c[3])
        : "r"(a[0]), "r"(a[1]), "r"(a[2]), "r"(a[3]), "r"(b0), "r"(b1));
}

__device__ __forceinline__ uint32_t packh2(float x, float y) {
    __half2 h(__float2half_rn(x), __float2half_rn(y));
    return *(uint32_t*)&h;
}

// Fast exp2 on the FMA pipe. NO clamp: inputs guaranteed in [-70, 0].
__device__ __forceinline__ float exp2_nc(float y) {
    float fe = y + 12582912.0f;
    int ei = __float_as_int(fe) << 23;
    float fr = y - (fe - 12582912.0f);
    float p = 0.0096181291f;
    p = fmaf(p, fr, 0.0555041087f);
    p = fmaf(p, fr, 0.2402264923f);
    p = fmaf(p, fr, 0.6931471806f);
    p = fmaf(p, fr, 1.0f);
    return __int_as_float(__float_as_int(p) + ei);
}

// ---------------------------------------------------------------------------
// Prep kernels
// ---------------------------------------------------------------------------
__global__ void rope_tab_kernel(const int* __restrict__ pos) {
    int idx = blockIdx.x * 256 + threadIdx.x;
    if (idx >= Sn * 32) return;
    int s = idx >> 5;
    int f = idx & 31;
    float inv = expf(-(float)f * (logf(10000.0f) / 32.0f));
    float a = (float)pos[s] * inv;
    g_cos[idx] = cosf(a);
    g_sin[idx] = sinf(a);
}

__global__ void convert_x_kernel(const float* __restrict__ x,
                                 __half* __restrict__ xf) {
    size_t i = ((size_t)blockIdx.x * 256 + threadIdx.x) * 4;
    float4 a = *(const float4*)(x + i);
    __half2 h2[2];
    h2[0] = __half2(__float2half_rn(a.x), __float2half_rn(a.y));
    h2[1] = __half2(__float2half_rn(a.z), __float2half_rn(a.w));
    *(uint2*)(xf + i) = *(uint2*)h2;
}

__global__ void transpose_half_kernel(const float* __restrict__ W0,
                                      const float* __restrict__ W1,
                                      const float* __restrict__ W2,
                                      const float* __restrict__ W3,
                                      __half* __restrict__ Th) {
    __shared__ float t[32][33];
    const float* W = (blockIdx.z == 0) ? W0
                   : (blockIdx.z == 1) ? W1
                   : (blockIdx.z == 2) ? W2 : W3;
    __half* T = Th + (size_t)blockIdx.z * Dn * Dn;
    int n0 = blockIdx.x * 32, k0 = blockIdx.y * 32;
    int tx = threadIdx.x;
#pragma unroll
    for (int i = threadIdx.y; i < 32; i += 8)
        t[i][tx] = W[(size_t)(k0 + i) * Dn + n0 + tx];
    __syncthreads();
#pragma unroll
    for (int i = threadIdx.y; i < 32; i += 8)
        T[(size_t)(n0 + i) * Dn + k0 + tx] = __float2half_rn(t[tx][i]);
}

// ---------------------------------------------------------------------------
// Fused QKV GEMM: 3-stage cp.async pipeline, ONE barrier per chunk.
// Per-iter order: wait -> sync -> load(c+2) -> compute(c).  Stages mod 3.
// ---------------------------------------------------------------------------
constexpr int TM = 128, TN = 128, TK = 64;
constexpr int NCHUNK = Dn / TK;       // 16
constexpr int ROWB = 144;
constexpr int PLANE = 128 * ROWB;     // 18432
constexpr int STAGE2 = 2 * PLANE;     // 36864
constexpr int GEMM_SMEM = 3 * STAGE2; // 110592

__global__ __launch_bounds__(256, 2) void gemm_qkv_kernel(
    const __half* __restrict__ A, const __half* __restrict__ Wall,
    __half* __restrict__ Qo, __half* __restrict__ Ko,
    __half* __restrict__ Vo) {
    extern __shared__ char smem[];
    const uint32_t sb = s2u(smem);
    const int tid = threadIdx.x;
    const int wid = tid >> 5, lane = tid & 31;
    const int warp_m = wid & 3, warp_n = wid >> 2;
    const int m0 = blockIdx.y * TM;
    const int n0g = blockIdx.x * TN;
    const int w = n0g >> 10;
    const int n0 = n0g & (Dn - 1);
    const __half* Bw = Wall + (size_t)w * Dn * Dn;

    float acc[2][8][4];
#pragma unroll
    for (int mf = 0; mf < 2; ++mf)
#pragma unroll
        for (int nf = 0; nf < 8; ++nf)
#pragma unroll
            for (int j = 0; j < 4; ++j) acc[mf][nf][j] = 0.0f;

    const int lrow = lane & 15;
    const int lcol = (lane >> 4) * 16;
    const uint32_t aOff = (uint32_t)((warp_m * 32 + lrow) * ROWB + lcol);
    const uint32_t bOff = (uint32_t)(PLANE + (warp_n * 64 + lrow) * ROWB + lcol);

    auto load_stage = [&](uint32_t stb, int k0) {
#pragma unroll
        for (int i = 0; i < 8; ++i) {
            int op = tid + i * 256;
            int plane = op >> 10;
            int wv = op & 1023;
            int r = wv >> 3, ch = wv & 7;
            uint32_t dst = stb + plane * PLANE + r * ROWB + ch * 16;
            if (plane == 0)
                cpa16(dst, A + (size_t)(m0 + r) * Dn + k0 + ch * 8);
            else
                cpa16(dst, Bw + (size_t)(n0 + r) * Dn + k0 + ch * 8);
        }
    };

    load_stage(sb, 0);
    CP_COMMIT();
    load_stage(sb + STAGE2, TK);
    CP_COMMIT();

    for (int c = 0; c < NCHUNK; ++c) {
        if (c + 1 < NCHUNK) { CP_WAIT1(); } else { CP_WAIT0(); }
        __syncthreads();
        if (c + 2 < NCHUNK) {
            load_stage(sb + ((c + 2) % 3) * STAGE2, (c + 2) * TK);
            CP_COMMIT();
        }

        const uint32_t stb = sb + (c % 3) * STAGE2;
#pragma unroll
        for (int ks = 0; ks < 4; ++ks) {
            const uint32_t kb = ks * 32;
            uint32_t ah[2][4];
            ldsm4(stb + aOff + kb, ah[0]);
            ldsm4(stb + aOff + 16 * ROWB + kb, ah[1]);
            uint32_t bf[4][4];
#pragma unroll
            for (int p = 0; p < 4; ++p)
                ldsm4(stb + bOff + p * 16 * ROWB + kb, bf[p]);
#pragma unroll
            for (int mf = 0; mf < 2; ++mf)
#pragma unroll
                for (int nf = 0; nf < 8; ++nf) {
                    const int pr = nf >> 1, wh = nf & 1;
                    mma_f16(acc[mf][nf], ah[mf], bf[pr][wh], bf[pr][2 + wh]);
                }
        }
    }

    // Epilogue: head-major fp16 with per-weight transform
    __half* out = (w == 0) ? Qo : (w == 1) ? Ko : Vo;
    const int gid = lane >> 2, tig = lane & 3;
#pragma unroll
    for (int mf = 0; mf < 2; ++mf)
#pragma unroll
        for (int nf = 0; nf < 8; ++nf) {
            const float* cc = acc[mf][nf];
            const int row0 = m0 + warp_m * 32 + mf * 16 + gid;
            const int dcol = nf * 8 + tig * 2;
            const int h = (n0 + warp_n * 64) >> 6;
#pragma unroll
            for (int rr = 0; rr < 2; ++rr) {
                const int row = row0 + rr * 8;
                const int b_ = row >> 11, s_ = row & (Sn - 1);
                float e0 = cc[rr * 2], e1 = cc[rr * 2 + 1];
                if (w < 2) {
                    const int f = nf * 4 + tig;
                    const float cz = g_cos[s_ * 32 + f];
                    const float sz = g_sin[s_ * 32 + f];
                    const float r1 = e0 * cz - e1 * sz;
                    const float r2 = e0 * sz + e1 * cz;
                    e0 = r1; e1 = r2;
                }
                if (w == 0) { e0 *= QSCALE; e1 *= QSCALE; }
                __half2 hv(__float2half_rn(e0), __float2half_rn(e1));
                *(uint32_t*)(out + (((size_t)b_ * Hn + h) * Sn + s_) * DKn +
                             dcol) = *(uint32_t*)&hv;
            }
        }
}

// ---------------------------------------------------------------------------
// Output projection GEMM: same 3-stage single-barrier pipeline, fp32 out.
// ---------------------------------------------------------------------------
__global__ __launch_bounds__(256, 2) void gemm_out_kernel(
    const __half* __restrict__ A, const __half* __restrict__ Bw,
    float* __restrict__ out) {
    extern __shared__ char smem[];
    const uint32_t sb = s2u(smem);
    const int tid = threadIdx.x;
    const int wid = tid >> 5, lane = tid & 31;
    const int warp_m = wid & 3, warp_n = wid >> 2;
    const int m0 = blockIdx.y * TM, n0 = blockIdx.x * TN;

    float acc[2][8][4];
#pragma unroll
    for (int mf = 0; mf < 2; ++mf)
#pragma unroll
        for (int nf = 0; nf < 8; ++nf)
#pragma unroll
            for (int j = 0; j < 4; ++j) acc[mf][nf][j] = 0.0f;

    const int lrow = lane & 15;
    const int lcol = (lane >> 4) * 16;
    const uint32_t aOff = (uint32_t)((warp_m * 32 + lrow) * ROWB + lcol);
    const uint32_t bOff = (uint32_t)(PLANE + (warp_n * 64 + lrow) * ROWB + lcol);

    auto load_stage = [&](uint32_t stb, int k0) {
#pragma unroll
        for (int i = 0; i < 8; ++i) {
            int op = tid + i * 256;
            int plane = op >> 10;
            int wv = op & 1023;
            int r = wv >> 3, ch = wv & 7;
            uint32_t dst = stb + plane * PLANE + r * ROWB + ch * 16;
            if (plane == 0)
                cpa16(dst, A + (size_t)(m0 + r) * Dn + k0 + ch * 8);
            else
                cpa16(dst, Bw + (size_t)(n0 + r) * Dn + k0 + ch * 8);
        }
    };

    load_stage(sb, 0);
    CP_COMMIT();
    load_stage(sb + STAGE2, TK);
    CP_COMMIT();

    for (int c = 0; c < NCHUNK; ++c) {
        if (c + 1 < NCHUNK) { CP_WAIT1(); } else { CP_WAIT0(); }
        __syncthreads();
        if (c + 2 < NCHUNK) {
            load_stage(sb + ((c + 2) % 3) * STAGE2, (c + 2) * TK);
            CP_COMMIT();
        }

        const uint32_t stb = sb + (c % 3) * STAGE2;
#pragma unroll
        for (int ks = 0; ks < 4; ++ks) {
            const uint32_t kb = ks * 32;
            uint32_t ah[2][4];
            ldsm4(stb + aOff + kb, ah[0]);
            ldsm4(stb + aOff + 16 * ROWB + kb, ah[1]);
            uint32_t bf[4][4];
#pragma unroll
            for (int p = 0; p < 4; ++p)
                ldsm4(stb + bOff + p * 16 * ROWB + kb, bf[p]);
#pragma unroll
            for (int mf = 0; mf < 2; ++mf)
#pragma unroll
                for (int nf = 0; nf < 8; ++nf) {
                    const int pr = nf >> 1, wh = nf & 1;
                    mma_f16(acc[mf][nf], ah[mf], bf[pr][wh], bf[pr][2 + wh]);
                }
        }
    }

    const int gid = lane >> 2, tig = lane & 3;
#pragma unroll
    for (int mf = 0; mf < 2; ++mf)
#pragma unroll
        for (int nf = 0; nf < 8; ++nf) {
            const float* cc = acc[mf][nf];
            const int row0 = m0 + warp_m * 32 + mf * 16 + gid;
            const int col = n0 + warp_n * 64 + nf * 8 + tig * 2;
            *(float2*)(out + (size_t)row0 * Dn + col) = make_float2(cc[0], cc[1]);
            *(float2*)(out + (size_t)(row0 + 8) * Dn + col) =
                make_float2(cc[2], cc[3]);
        }
}

// ---------------------------------------------------------------------------
// Flash attention: 3-stage single-barrier KV pipeline; P in registers (FA2);
// row-sum via ones-column MMA; rescale skipped when max unchanged.
// ---------------------------------------------------------------------------
constexpr int KVSB = 144;
constexpr int KVPLANE = 64 * KVSB;              // 9216
constexpr int STAGE_B = 2 * KVPLANE;            // 18432
constexpr int ATTN_SMEM = 3 * STAGE_B;          // 55296

__device__ __forceinline__ void load_kv(uint32_t dstb,
                                        const __half* __restrict__ Kb,
                                        const __half* __restrict__ Vb, int kt,
                                        int tid) {
    const __half* s0 = Kb + (size_t)kt * 64 * 64;
    const __half* s1 = Vb + (size_t)kt * 64 * 64;
#pragma unroll
    for (int i = 0; i < 4; ++i) {
        int idx = tid + i * 256;
        int t = idx >> 9;
        int w = idx & 511;
        int r = w >> 3, ch = w & 7;
        uint32_t d = dstb + (uint32_t)(t * KVPLANE + r * KVSB + ch * 16);
        const __half* s = (t ? s1 : s0) + r * 64 + ch * 8;
        cpa16(d, s);
    }
}

__global__ __launch_bounds__(256, 2) void attn_tc_kernel(
    const __half* __restrict__ Q, const __half* __restrict__ K,
    const __half* __restrict__ V, __half* __restrict__ Oh) {
    extern __shared__ char smc[];
    const uint32_t smb = s2u(smc);
    const int tid = threadIdx.x;
    const int wid = tid >> 5, lane = tid & 31;
    const int gid = lane >> 2, tig = lane & 3;
    const int bh = blockIdx.y;
    const int qt = (int)gridDim.x - 1 - (int)blockIdx.x;
    const int q0 = qt * 128;

    const __half* Qb = Q + ((size_t)bh * Sn + q0) * DKn;
    const __half* Kb = K + (size_t)bh * Sn * DKn;
    const __half* Vb = V + (size_t)bh * Sn * DKn;

    const int lr = wid * 16 + gid;
    uint32_t aq[4][4];
#pragma unroll
    for (int kf = 0; kf < 4; ++kf) {
        const __half* p = Qb + (size_t)lr * DKn + kf * 16 + tig * 2;
        aq[kf][0] = *(const uint32_t*)(p);
        aq[kf][1] = *(const uint32_t*)(p + 8 * DKn);
        aq[kf][2] = *(const uint32_t*)(p + 8);
        aq[kf][3] = *(const uint32_t*)(p + 8 * DKn + 8);
    }

    float oacc[8][4];
#pragma unroll
    for (int nf = 0; nf < 8; ++nf)
#pragma unroll
        for (int j = 0; j < 4; ++j) oacc[nf][j] = 0.0f;
    float lacc[4] = {0.0f, 0.0f, 0.0f, 0.0f};
    float mr0 = 0.0f, mr1 = 0.0f;   // true row max >= 0 (diagonal self-logit)
    const uint32_t ONES = 0x3C003C00u;

    const int nkt = 2 * qt + 2;     // always >= 2
    load_kv(smb, Kb, Vb, 0, tid);
    CP_COMMIT();
    load_kv(smb + STAGE_B, Kb, Vb, 1, tid);
    CP_COMMIT();

    const int lrow = lane & 15;
    const uint32_t kOffBase = (uint32_t)(lrow * KVSB + (lane >> 4) * 16);
    const uint32_t vOffBase = (uint32_t)(lrow * KVSB + (lane >> 4) * 16);

    for (int kt = 0; kt < nkt; ++kt) {
        if (kt + 1 < nkt) { CP_WAIT1(); } else { CP_WAIT0(); }
        __syncthreads();
        if (kt + 2 < nkt) {
            load_kv(smb + ((kt + 2) % 3) * STAGE_B, Kb, Vb, kt + 2, tid);
            CP_COMMIT();
        }

        // Warps 0-3 (rows q0..q0+63) have every key masked in tile 2qt+1.
        if (!(kt == 2 * qt + 1 && wid < 4)) {
            const uint32_t Ks = smb + (kt % 3) * STAGE_B;
            const uint32_t Vs = Ks + KVPLANE;

            float sacc[8][4];
#pragma unroll
            for (int nf = 0; nf < 8; ++nf)
#pragma unroll
                for (int j = 0; j < 4; ++j) sacc[nf][j] = 0.0f;
#pragma unroll
            for (int kf = 0; kf < 4; ++kf) {
                uint32_t bk[4][4];
#pragma unroll
                for (int p = 0; p < 4; ++p)
                    ldsm4(Ks + kOffBase + p * 16 * KVSB + kf * 32, bk[p]);
#pragma unroll
                for (int p = 0; p < 4; ++p) {
                    mma_f16(sacc[2 * p], aq[kf], bk[p][0], bk[p][2]);
                    mma_f16(sacc[2 * p + 1], aq[kf], bk[p][1], bk[p][3]);
                }
            }

            if (kt >= 2 * qt) {
                const int cb = kt * 64 + tig * 2;
                const int r0g = q0 + lr;
#pragma unroll
                for (int nf = 0; nf < 8; ++nf) {
                    const int c0 = cb + nf * 8;
                    if (c0 > r0g) sacc[nf][0] = MASKV;
                    if (c0 + 1 > r0g) sacc[nf][1] = MASKV;
                    if (c0 > r0g + 8) sacc[nf][2] = MASKV;
                    if (c0 + 1 > r0g + 8) sacc[nf][3] = MASKV;
                }
            }

            float t0 = MASKV, t1 = MASKV;
#pragma unroll
            for (int nf = 0; nf < 8; ++nf) {
                t0 = fmaxf(t0, fmaxf(sacc[nf][0], sacc[nf][1]));
                t1 = fmaxf(t1, fmaxf(sacc[nf][2], sacc[nf][3]));
            }
            t0 = fmaxf(t0, __shfl_xor_sync(0xffffffffu, t0, 1));
            t0 = fmaxf(t0, __shfl_xor_sync(0xffffffffu, t0, 2));
            t1 = fmaxf(t1, __shfl_xor_sync(0xffffffffu, t1, 1));
            t1 = fmaxf(t1, __shfl_xor_sync(0xffffffffu, t1, 2));
            const float nm0 = fmaxf(mr0, t0), nm1 = fmaxf(mr1, t1);

            // Skip rescale when no row max changed anywhere in the warp
            // (cr == 1 exactly; skipped multiplies are identity).
            const bool nochg = __all_sync(0xffffffffu,
                                          (nm0 == mr0) && (nm1 == mr1));
            if (!nochg) {
                const float cr0 = exp2_nc(mr0 - nm0);
                const float cr1 = exp2_nc(mr1 - nm1);
                lacc[0] *= cr0;
                lacc[1] *= cr0;
                lacc[2] *= cr1;
                lacc[3] *= cr1;
#pragma unroll
                for (int nf = 0; nf < 8; ++nf) {
                    oacc[nf][0] *= cr0;
                    oacc[nf][1] *= cr0;
                    oacc[nf][2] *= cr1;
                    oacc[nf][3] *= cr1;
                }
            }
            mr0 = nm0; mr1 = nm1;

#pragma unroll
            for (int nf = 0; nf < 8; ++nf) {
                sacc[nf][0] = exp2_nc(sacc[nf][0] - nm0);
                sacc[nf][1] = exp2_nc(sacc[nf][1] - nm0);
                sacc[nf][2] = exp2_nc(sacc[nf][2] - nm1);
                sacc[nf][3] = exp2_nc(sacc[nf][3] - nm1);
            }

            // O += P . V ; l += P . 1
#pragma unroll
            for (int kf = 0; kf < 4; ++kf) {
                uint32_t ap[4];
                ap[0] = packh2(sacc[2 * kf][0], sacc[2 * kf][1]);
                ap[1] = packh2(sacc[2 * kf][2], sacc[2 * kf][3]);
                ap[2] = packh2(sacc[2 * kf + 1][0], sacc[2 * kf + 1][1]);
                ap[3] = packh2(sacc[2 * kf + 1][2], sacc[2 * kf + 1][3]);
                mma_f16(lacc, ap, ONES, ONES);
#pragma unroll
                for (int p = 0; p < 4; ++p) {
                    uint32_t bv[4];
                    ldsm4t(Vs + (uint32_t)(kf * 16 * KVSB) + vOffBase +
                               (uint32_t)(p * 32),
                           bv);
                    mma_f16(oacc[2 * p], ap, bv[0], bv[1]);
                    mma_f16(oacc[2 * p + 1], ap, bv[2], bv[3]);
                }
            }
        }
    }

    const float il0 = 1.0f / lacc[0], il1 = 1.0f / lacc[2];
    const int row0 = q0 + lr;
    const int b_ = bh >> 4, h = bh & 15;
    const size_t o0 = ((size_t)b_ * Sn + row0) * Dn + h * DKn;
    const size_t o1 = o0 + (size_t)8 * Dn;
#pragma unroll
    for (int nf = 0; nf < 8; ++nf) {
        const int col = nf * 8 + tig * 2;
        __half2 hv0(__float2half_rn(oacc[nf][0] * il0),
                    __float2half_rn(oacc[nf][1] * il0));
        __half2 hv1(__float2half_rn(oacc[nf][2] * il1),
                    __float2half_rn(oacc[nf][3] * il1));
        *(uint32_t*)(Oh + o0 + col) = *(uint32_t*)&hv0;
        *(uint32_t*)(Oh + o1 + col) = *(uint32_t*)&hv1;
    }
}

// ---------------------------------------------------------------------------
extern "C" void kernel_launch(void* const* d_in, const int* in_sizes, int n_in,
                              void* d_out, int out_size) {
    const float* x  = (const float*)d_in[0];
    const float* Wq = (const float*)d_in[1];
    const float* Wk = (const float*)d_in[2];
    const float* Wv = (const float*)d_in[3];
    const float* Wo = (const float*)d_in[4];
    const int* pos  = (const int*)d_in[5];

    __half *pxf, *pWh, *pQ, *pK, *pV, *pah;
    cudaGetSymbolAddress((void**)&pxf, g_xf);
    cudaGetSymbolAddress((void**)&pWh, g_Wh);
    cudaGetSymbolAddress((void**)&pQ, g_Q);
    cudaGetSymbolAddress((void**)&pK, g_K);
    cudaGetSymbolAddress((void**)&pV, g_V);
    cudaGetSymbolAddress((void**)&pah, g_ah);

    cudaFuncSetAttribute((const void*)gemm_qkv_kernel,
                         cudaFuncAttributeMaxDynamicSharedMemorySize, GEMM_SMEM);
    cudaFuncSetAttribute((const void*)gemm_qkv_kernel,
                         cudaFuncAttributePreferredSharedMemoryCarveout, 100);
    cudaFuncSetAttribute((const void*)gemm_out_kernel,
                         cudaFuncAttributeMaxDynamicSharedMemorySize, GEMM_SMEM);
    cudaFuncSetAttribute((const void*)gemm_out_kernel,
                         cudaFuncAttributePreferredSharedMemoryCarveout, 100);
    cudaFuncSetAttribute((const void*)attn_tc_kernel,
                         cudaFuncAttributeMaxDynamicSharedMemorySize, ATTN_SMEM);

    rope_tab_kernel<<<(Sn * 32 + 255) / 256, 256>>>(pos);
    convert_x_kernel<<<Mn * Dn / 1024, 256>>>(x, pxf);
    transpose_half_kernel<<<dim3(32, 32, 4), dim3(32, 8)>>>(Wq, Wk, Wv, Wo, pWh);

    dim3 gqkv(3 * Dn / TN, Mn / TM);  // (24, 64)
    gemm_qkv_kernel<<<gqkv, 256, GEMM_SMEM>>>(pxf, pWh, pQ, pK, pV);

    dim3 agrid(Sn / 128, Bn * Hn);  // (16, 64)
    attn_tc_kernel<<<agrid, 256, ATTN_SMEM>>>(pQ, pK, pV, pah);

    dim3 gout(Dn / TN, Mn / TM);  // (8, 64)
    gemm_out_kernel<<<gout, 256, GEMM_SMEM>>>(pah, pWh + 3 * (size_t)Dn * Dn,
                                              (float*)d_out);
}

// round 17
// speedup vs baseline: 1.0089x; 1.0089x over previous
#include <cuda_runtime.h>
#include <cuda_fp16.h>
#include <math.h>
#include <cstdint>

// Problem constants
constexpr int Bn = 4;
constexpr int Sn = 2048;
constexpr int Dn = 1024;
constexpr int Hn = 16;
constexpr int DKn = 64;
constexpr int Mn = Bn * Sn;  // 8192

// Q pre-scale: 1/sqrt(64) * log2(e)
#define QSCALE 0.18033688011112042f
// Masked-score value (row max >= 0 via diagonal self-logit)
#define MASKV -64.0f

// ---------------------------------------------------------------------------
// Scratch (static device arrays — no allocation allowed)
// ---------------------------------------------------------------------------
__device__ __half g_xf[Mn * Dn];
__device__ __half g_Wh[4 * Dn * Dn];
__device__ __half g_Q[Mn * Dn];
__device__ __half g_K[Mn * Dn];
__device__ __half g_V[Mn * Dn];
__device__ __half g_ah[Mn * Dn];
__device__ float g_cos[Sn * 32];
__device__ float g_sin[Sn * 32];

// ---------------------------------------------------------------------------
// PTX helpers
// ---------------------------------------------------------------------------
__device__ __forceinline__ uint32_t s2u(const void* p) {
    uint32_t a;
    asm("{ .reg .u64 t; cvta.to.shared.u64 t, %1; cvt.u32.u64 %0, t; }"
        : "=r"(a) : "l"(p));
    return a;
}

__device__ __forceinline__ void cpa16(uint32_t dst, const void* src) {
    asm volatile("cp.async.cg.shared.global [%0], [%1], 16;"
                 :: "r"(dst), "l"(src) : "memory");
}
#define CP_COMMIT() asm volatile("cp.async.commit_group;" ::: "memory")
#define CP_WAIT1() asm volatile("cp.async.wait_group 1;" ::: "memory")
#define CP_WAIT0() asm volatile("cp.async.wait_group 0;" ::: "memory")

__device__ __forceinline__ void ldsm4(uint32_t addr, uint32_t* r) {
    asm volatile(
        "ldmatrix.sync.aligned.m8n8.x4.shared.b16 {%0,%1,%2,%3}, [%4];"
        : "=r"(r[0]), "=r"(r[1]), "=r"(r[2]), "=r"(r[3]) : "r"(addr));
}

__device__ __forceinline__ void ldsm4t(uint32_t addr, uint32_t* r) {
    asm volatile(
        "ldmatrix.sync.aligned.m8n8.x4.trans.shared.b16 {%0,%1,%2,%3}, [%4];"
        : "=r"(r[0]), "=r"(r[1]), "=r"(r[2]), "=r"(r[3]) : "r"(addr));
}

__device__ __forceinline__ void mma_f16(float* c, const uint32_t* a,
                                        uint32_t b0, uint32_t b1) {
    asm volatile(
        "mma.sync.aligned.m16n8k16.row.col.f32.f16.f16.f32 "
        "{%0,%1,%2,%3}, {%4,%5,%6,%7}, {%8,%9}, {%0,%1,%2,%3};"
        : "+f"(c[0]), "+f"(c[1]), "+f"(c[2]), "+f"(c[3])
        : "r"(a[0]), "r"(a[1]), "r"(a[2]), "r"(a[3]), "r"(b0), "r"(b1));
}

__device__ __forceinline__ uint32_t packh2(float x, float y) {
    __half2 h(__float2half_rn(x), __float2half_rn(y));
    return *(uint32_t*)&h;
}

// Fast exp2 on the FMA pipe. NO clamp: inputs guaranteed in [-70, 0].
__device__ __forceinline__ float exp2_nc(float y) {
    float fe = y + 12582912.0f;
    int ei = __float_as_int(fe) << 23;
    float fr = y - (fe - 12582912.0f);
    float p = 0.0096181291f;
    p = fmaf(p, fr, 0.0555041087f);
    p = fmaf(p, fr, 0.2402264923f);
    p = fmaf(p, fr, 0.6931471806f);
    p = fmaf(p, fr, 1.0f);
    return __int_as_float(__float_as_int(p) + ei);
}

// ---------------------------------------------------------------------------
// Prep kernels
// ---------------------------------------------------------------------------
__global__ void rope_tab_kernel(const int* __restrict__ pos) {
    int idx = blockIdx.x * 256 + threadIdx.x;
    if (idx >= Sn * 32) return;
    int s = idx >> 5;
    int f = idx & 31;
    float inv = expf(-(float)f * (logf(10000.0f) / 32.0f));
    float a = (float)pos[s] * inv;
    g_cos[idx] = cosf(a);
    g_sin[idx] = sinf(a);
}

__global__ void convert_x_kernel(const float* __restrict__ x,
                                 __half* __restrict__ xf) {
    size_t i = ((size_t)blockIdx.x * 256 + threadIdx.x) * 4;
    float4 a = *(const float4*)(x + i);
    __half2 h2[2];
    h2[0] = __half2(__float2half_rn(a.x), __float2half_rn(a.y));
    h2[1] = __half2(__float2half_rn(a.z), __float2half_rn(a.w));
    *(uint2*)(xf + i) = *(uint2*)h2;
}

__global__ void transpose_half_kernel(const float* __restrict__ W0,
                                      const float* __restrict__ W1,
                                      const float* __restrict__ W2,
                                      const float* __restrict__ W3,
                                      __half* __restrict__ Th) {
    __shared__ float t[32][33];
    const float* W = (blockIdx.z == 0) ? W0
                   : (blockIdx.z == 1) ? W1
                   : (blockIdx.z == 2) ? W2 : W3;
    __half* T = Th + (size_t)blockIdx.z * Dn * Dn;
    int n0 = blockIdx.x * 32, k0 = blockIdx.y * 32;
    int tx = threadIdx.x;
#pragma unroll
    for (int i = threadIdx.y; i < 32; i += 8)
        t[i][tx] = W[(size_t)(k0 + i) * Dn + n0 + tx];
    __syncthreads();
#pragma unroll
    for (int i = threadIdx.y; i < 32; i += 8)
        T[(size_t)(n0 + i) * Dn + k0 + tx] = __float2half_rn(t[tx][i]);
}

// ---------------------------------------------------------------------------
// Fused QKV GEMM (R15-proven): CTA 128x128, K-chunk 64, 2-stage cp.async.
// ---------------------------------------------------------------------------
constexpr int TM = 128, TN = 128, TK = 64;
constexpr int NCHUNK = Dn / TK;       // 16
constexpr int ROWB = 144;
constexpr int PLANE = 128 * ROWB;     // 18432
constexpr int STAGE2 = 2 * PLANE;     // 36864
constexpr int GEMM_SMEM = 2 * STAGE2; // 73728

__global__ __launch_bounds__(256, 2) void gemm_qkv_kernel(
    const __half* __restrict__ A, const __half* __restrict__ Wall,
    __half* __restrict__ Qo, __half* __restrict__ Ko,
    __half* __restrict__ Vo) {
    extern __shared__ char smem[];
    const uint32_t sb = s2u(smem);
    const int tid = threadIdx.x;
    const int wid = tid >> 5, lane = tid & 31;
    const int warp_m = wid & 3, warp_n = wid >> 2;
    const int m0 = blockIdx.y * TM;
    const int n0g = blockIdx.x * TN;
    const int w = n0g >> 10;
    const int n0 = n0g & (Dn - 1);
    const __half* Bw = Wall + (size_t)w * Dn * Dn;

    float acc[2][8][4];
#pragma unroll
    for (int mf = 0; mf < 2; ++mf)
#pragma unroll
        for (int nf = 0; nf < 8; ++nf)
#pragma unroll
            for (int j = 0; j < 4; ++j) acc[mf][nf][j] = 0.0f;

    const int lrow = lane & 15;
    const int lcol = (lane >> 4) * 16;
    const uint32_t aOff = (uint32_t)((warp_m * 32 + lrow) * ROWB + lcol);
    const uint32_t bOff = (uint32_t)(PLANE + (warp_n * 64 + lrow) * ROWB + lcol);

    auto load_stage = [&](uint32_t stb, int k0) {
#pragma unroll
        for (int i = 0; i < 8; ++i) {
            int op = tid + i * 256;
            int plane = op >> 10;
            int wv = op & 1023;
            int r = wv >> 3, ch = wv & 7;
            uint32_t dst = stb + plane * PLANE + r * ROWB + ch * 16;
            if (plane == 0)
                cpa16(dst, A + (size_t)(m0 + r) * Dn + k0 + ch * 8);
            else
                cpa16(dst, Bw + (size_t)(n0 + r) * Dn + k0 + ch * 8);
        }
    };

    load_stage(sb, 0);
    CP_COMMIT();

    for (int c = 0; c < NCHUNK; ++c) {
        if (c + 1 < NCHUNK) {
            load_stage(sb + ((c + 1) & 1) * STAGE2, (c + 1) * TK);
            CP_COMMIT();
            CP_WAIT1();
        } else {
            CP_WAIT0();
        }
        __syncthreads();

        const uint32_t stb = sb + (c & 1) * STAGE2;
#pragma unroll
        for (int ks = 0; ks < 4; ++ks) {
            const uint32_t kb = ks * 32;
            uint32_t ah[2][4];
            ldsm4(stb + aOff + kb, ah[0]);
            ldsm4(stb + aOff + 16 * ROWB + kb, ah[1]);
            uint32_t bf[4][4];
#pragma unroll
            for (int p = 0; p < 4; ++p)
                ldsm4(stb + bOff + p * 16 * ROWB + kb, bf[p]);
#pragma unroll
            for (int mf = 0; mf < 2; ++mf)
#pragma unroll
                for (int nf = 0; nf < 8; ++nf) {
                    const int pr = nf >> 1, wh = nf & 1;
                    mma_f16(acc[mf][nf], ah[mf], bf[pr][wh], bf[pr][2 + wh]);
                }
        }
        __syncthreads();
    }

    // Epilogue: head-major fp16 with per-weight transform
    __half* out = (w == 0) ? Qo : (w == 1) ? Ko : Vo;
    const int gid = lane >> 2, tig = lane & 3;
#pragma unroll
    for (int mf = 0; mf < 2; ++mf)
#pragma unroll
        for (int nf = 0; nf < 8; ++nf) {
            const float* cc = acc[mf][nf];
            const int row0 = m0 + warp_m * 32 + mf * 16 + gid;
            const int dcol = nf * 8 + tig * 2;
            const int h = (n0 + warp_n * 64) >> 6;
#pragma unroll
            for (int rr = 0; rr < 2; ++rr) {
                const int row = row0 + rr * 8;
                const int b_ = row >> 11, s_ = row & (Sn - 1);
                float e0 = cc[rr * 2], e1 = cc[rr * 2 + 1];
                if (w < 2) {
                    const int f = nf * 4 + tig;
                    const float cz = g_cos[s_ * 32 + f];
                    const float sz = g_sin[s_ * 32 + f];
                    const float r1 = e0 * cz - e1 * sz;
                    const float r2 = e0 * sz + e1 * cz;
                    e0 = r1; e1 = r2;
                }
                if (w == 0) { e0 *= QSCALE; e1 *= QSCALE; }
                __half2 hv(__float2half_rn(e0), __float2half_rn(e1));
                *(uint32_t*)(out + (((size_t)b_ * Hn + h) * Sn + s_) * DKn +
                             dcol) = *(uint32_t*)&hv;
            }
        }
}

// ---------------------------------------------------------------------------
// Output projection GEMM: CTA 128x64 (better wave balance: 1024 CTAs),
// K-chunk 64, 2-stage cp.async pipeline, fp32 out.
// ---------------------------------------------------------------------------
constexpr int TNO = 64;
constexpr int PLANE_BO = 64 * ROWB;        // 9216
constexpr int STAGEO = PLANE + PLANE_BO;   // 27648
constexpr int OUT_SMEM = 2 * STAGEO;       // 55296

__global__ __launch_bounds__(256, 2) void gemm_out_kernel(
    const __half* __restrict__ A, const __half* __restrict__ Bw,
    float* __restrict__ out) {
    extern __shared__ char smem[];
    const uint32_t sb = s2u(smem);
    const int tid = threadIdx.x;
    const int wid = tid >> 5, lane = tid & 31;
    const int warp_m = wid & 3, warp_n = wid >> 2;   // warp tile 32(M) x 32(N)
    const int m0 = blockIdx.y * TM, n0 = blockIdx.x * TNO;

    float acc[2][4][4];
#pragma unroll
    for (int mf = 0; mf < 2; ++mf)
#pragma unroll
        for (int nf = 0; nf < 4; ++nf)
#pragma unroll
            for (int j = 0; j < 4; ++j) acc[mf][nf][j] = 0.0f;

    const int lrow = lane & 15;
    const int lcol = (lane >> 4) * 16;
    const uint32_t aOff = (uint32_t)((warp_m * 32 + lrow) * ROWB + lcol);
    const uint32_t bOff = (uint32_t)(PLANE + (warp_n * 32 + lrow) * ROWB + lcol);

    // stage: 128 A rows + 64 B rows, 8 x 16B chunks each = 1536 ops, 6/thread
    auto load_stage = [&](uint32_t stb, int k0) {
#pragma unroll
        for (int i = 0; i < 6; ++i) {
            int op = tid + i * 256;
            if (op < 1024) {
                int r = op >> 3, ch = op & 7;
                cpa16(stb + r * ROWB + ch * 16,
                      A + (size_t)(m0 + r) * Dn + k0 + ch * 8);
            } else {
                int wv = op - 1024;
                int r = wv >> 3, ch = wv & 7;
                cpa16(stb + PLANE + r * ROWB + ch * 16,
                      Bw + (size_t)(n0 + r) * Dn + k0 + ch * 8);
            }
        }
    };

    load_stage(sb, 0);
    CP_COMMIT();

    for (int c = 0; c < NCHUNK; ++c) {
        if (c + 1 < NCHUNK) {
            load_stage(sb + ((c + 1) & 1) * STAGEO, (c + 1) * TK);
            CP_COMMIT();
            CP_WAIT1();
        } else {
            CP_WAIT0();
        }
        __syncthreads();

        const uint32_t stb = sb + (c & 1) * STAGEO;
#pragma unroll
        for (int ks = 0; ks < 4; ++ks) {
            const uint32_t kb = ks * 32;
            uint32_t ah[2][4];
            ldsm4(stb + aOff + kb, ah[0]);
            ldsm4(stb + aOff + 16 * ROWB + kb, ah[1]);
            uint32_t bf[2][4];
#pragma unroll
            for (int p = 0; p < 2; ++p)
                ldsm4(stb + bOff + p * 16 * ROWB + kb, bf[p]);
#pragma unroll
            for (int mf = 0; mf < 2; ++mf)
#pragma unroll
                for (int nf = 0; nf < 4; ++nf) {
                    const int pr = nf >> 1, wh = nf & 1;
                    mma_f16(acc[mf][nf], ah[mf], bf[pr][wh], bf[pr][2 + wh]);
                }
        }
        __syncthreads();
    }

    const int gid = lane >> 2, tig = lane & 3;
#pragma unroll
    for (int mf = 0; mf < 2; ++mf)
#pragma unroll
        for (int nf = 0; nf < 4; ++nf) {
            const float* cc = acc[mf][nf];
            const int row0 = m0 + warp_m * 32 + mf * 16 + gid;
            const int col = n0 + warp_n * 32 + nf * 8 + tig * 2;
            *(float2*)(out + (size_t)row0 * Dn + col) = make_float2(cc[0], cc[1]);
            *(float2*)(out + (size_t)(row0 + 8) * Dn + col) =
                make_float2(cc[2], cc[3]);
        }
}

// ---------------------------------------------------------------------------
// Flash attention (R15-proven 2-stage) + rescale-skip when max unchanged.
// P in registers (FA2); row-sum via ones-column MMA; clamp-free exp2;
// fully-masked tiles skipped.
// ---------------------------------------------------------------------------
constexpr int KVSB = 144;
constexpr int KVPLANE = 64 * KVSB;              // 9216
constexpr int STAGE_B = 2 * KVPLANE;            // 18432
constexpr int ATTN_SMEM = 2 * STAGE_B;          // 36864

__device__ __forceinline__ void load_kv(uint32_t dstb,
                                        const __half* __restrict__ Kb,
                                        const __half* __restrict__ Vb, int kt,
                                        int tid) {
    const __half* s0 = Kb + (size_t)kt * 64 * 64;
    const __half* s1 = Vb + (size_t)kt * 64 * 64;
#pragma unroll
    for (int i = 0; i < 4; ++i) {
        int idx = tid + i * 256;
        int t = idx >> 9;
        int w = idx & 511;
        int r = w >> 3, ch = w & 7;
        uint32_t d = dstb + (uint32_t)(t * KVPLANE + r * KVSB + ch * 16);
        const __half* s = (t ? s1 : s0) + r * 64 + ch * 8;
        cpa16(d, s);
    }
}

__global__ __launch_bounds__(256, 2) void attn_tc_kernel(
    const __half* __restrict__ Q, const __half* __restrict__ K,
    const __half* __restrict__ V, __half* __restrict__ Oh) {
    extern __shared__ char smc[];
    const uint32_t smb = s2u(smc);
    const int tid = threadIdx.x;
    const int wid = tid >> 5, lane = tid & 31;
    const int gid = lane >> 2, tig = lane & 3;
    const int bh = blockIdx.y;
    const int qt = (int)gridDim.x - 1 - (int)blockIdx.x;
    const int q0 = qt * 128;

    const __half* Qb = Q + ((size_t)bh * Sn + q0) * DKn;
    const __half* Kb = K + (size_t)bh * Sn * DKn;
    const __half* Vb = V + (size_t)bh * Sn * DKn;

    const int lr = wid * 16 + gid;
    uint32_t aq[4][4];
#pragma unroll
    for (int kf = 0; kf < 4; ++kf) {
        const __half* p = Qb + (size_t)lr * DKn + kf * 16 + tig * 2;
        aq[kf][0] = *(const uint32_t*)(p);
        aq[kf][1] = *(const uint32_t*)(p + 8 * DKn);
        aq[kf][2] = *(const uint32_t*)(p + 8);
        aq[kf][3] = *(const uint32_t*)(p + 8 * DKn + 8);
    }

    float oacc[8][4];
#pragma unroll
    for (int nf = 0; nf < 8; ++nf)
#pragma unroll
        for (int j = 0; j < 4; ++j) oacc[nf][j] = 0.0f;
    float lacc[4] = {0.0f, 0.0f, 0.0f, 0.0f};
    float mr0 = 0.0f, mr1 = 0.0f;
    const uint32_t ONES = 0x3C003C00u;

    const int nkt = 2 * qt + 2;
    load_kv(smb, Kb, Vb, 0, tid);
    CP_COMMIT();

    const int lrow = lane & 15;
    const uint32_t kOffBase = (uint32_t)(lrow * KVSB + (lane >> 4) * 16);
    const uint32_t vOffBase = (uint32_t)(lrow * KVSB + (lane >> 4) * 16);

    for (int kt = 0; kt < nkt; ++kt) {
        if (kt + 1 < nkt) {
            load_kv(smb + ((kt + 1) & 1) * STAGE_B, Kb, Vb, kt + 1, tid);
            CP_COMMIT();
            CP_WAIT1();
        } else {
            CP_WAIT0();
        }
        __syncthreads();

        if (!(kt == 2 * qt + 1 && wid < 4)) {
            const uint32_t Ks = smb + (kt & 1) * STAGE_B;
            const uint32_t Vs = Ks + KVPLANE;

            float sacc[8][4];
#pragma unroll
            for (int nf = 0; nf < 8; ++nf)
#pragma unroll
                for (int j = 0; j < 4; ++j) sacc[nf][j] = 0.0f;
#pragma unroll
            for (int kf = 0; kf < 4; ++kf) {
                uint32_t bk[4][4];
#pragma unroll
                for (int p = 0; p < 4; ++p)
                    ldsm4(Ks + kOffBase + p * 16 * KVSB + kf * 32, bk[p]);
#pragma unroll
                for (int p = 0; p < 4; ++p) {
                    mma_f16(sacc[2 * p], aq[kf], bk[p][0], bk[p][2]);
                    mma_f16(sacc[2 * p + 1], aq[kf], bk[p][1], bk[p][3]);
                }
            }

            if (kt >= 2 * qt) {
                const int cb = kt * 64 + tig * 2;
                const int r0g = q0 + lr;
#pragma unroll
                for (int nf = 0; nf < 8; ++nf) {
                    const int c0 = cb + nf * 8;
                    if (c0 > r0g) sacc[nf][0] = MASKV;
                    if (c0 + 1 > r0g) sacc[nf][1] = MASKV;
                    if (c0 > r0g + 8) sacc[nf][2] = MASKV;
                    if (c0 + 1 > r0g + 8) sacc[nf][3] = MASKV;
                }
            }

            float t0 = MASKV, t1 = MASKV;
#pragma unroll
            for (int nf = 0; nf < 8; ++nf) {
                t0 = fmaxf(t0, fmaxf(sacc[nf][0], sacc[nf][1]));
                t1 = fmaxf(t1, fmaxf(sacc[nf][2], sacc[nf][3]));
            }
            t0 = fmaxf(t0, __shfl_xor_sync(0xffffffffu, t0, 1));
            t0 = fmaxf(t0, __shfl_xor_sync(0xffffffffu, t0, 2));
            t1 = fmaxf(t1, __shfl_xor_sync(0xffffffffu, t1, 1));
            t1 = fmaxf(t1, __shfl_xor_sync(0xffffffffu, t1, 2));
            const float nm0 = fmaxf(mr0, t0), nm1 = fmaxf(mr1, t1);

            // Skip rescale when no row max changed in the warp (cr == 1).
            const bool nochg = __all_sync(0xffffffffu,
                                          (nm0 == mr0) && (nm1 == mr1));
            if (!nochg) {
                const float cr0 = exp2_nc(mr0 - nm0);
                const float cr1 = exp2_nc(mr1 - nm1);
                lacc[0] *= cr0;
                lacc[1] *= cr0;
                lacc[2] *= cr1;
                lacc[3] *= cr1;
#pragma unroll
                for (int nf = 0; nf < 8; ++nf) {
                    oacc[nf][0] *= cr0;
                    oacc[nf][1] *= cr0;
                    oacc[nf][2] *= cr1;
                    oacc[nf][3] *= cr1;
                }
            }
            mr0 = nm0; mr1 = nm1;

#pragma unroll
            for (int nf = 0; nf < 8; ++nf) {
                sacc[nf][0] = exp2_nc(sacc[nf][0] - nm0);
                sacc[nf][1] = exp2_nc(sacc[nf][1] - nm0);
                sacc[nf][2] = exp2_nc(sacc[nf][2] - nm1);
                sacc[nf][3] = exp2_nc(sacc[nf][3] - nm1);
            }

            // O += P . V ; l += P . 1
#pragma unroll
            for (int kf = 0; kf < 4; ++kf) {
                uint32_t ap[4];
                ap[0] = packh2(sacc[2 * kf][0], sacc[2 * kf][1]);
                ap[1] = packh2(sacc[2 * kf][2], sacc[2 * kf][3]);
                ap[2] = packh2(sacc[2 * kf + 1][0], sacc[2 * kf + 1][1]);
                ap[3] = packh2(sacc[2 * kf + 1][2], sacc[2 * kf + 1][3]);
                mma_f16(lacc, ap, ONES, ONES);
#pragma unroll
                for (int p = 0; p < 4; ++p) {
                    uint32_t bv[4];
                    ldsm4t(Vs + (uint32_t)(kf * 16 * KVSB) + vOffBase +
                               (uint32_t)(p * 32),
                           bv);
                    mma_f16(oacc[2 * p], ap, bv[0], bv[1]);
                    mma_f16(oacc[2 * p + 1], ap, bv[2], bv[3]);
                }
            }
        }
        __syncthreads();
    }

    const float il0 = 1.0f / lacc[0], il1 = 1.0f / lacc[2];
    const int row0 = q0 + lr;
    const int b_ = bh >> 4, h = bh & 15;
    const size_t o0 = ((size_t)b_ * Sn + row0) * Dn + h * DKn;
    const size_t o1 = o0 + (size_t)8 * Dn;
#pragma unroll
    for (int nf = 0; nf < 8; ++nf) {
        const int col = nf * 8 + tig * 2;
        __half2 hv0(__float2half_rn(oacc[nf][0] * il0),
                    __float2half_rn(oacc[nf][1] * il0));
        __half2 hv1(__float2half_rn(oacc[nf][2] * il1),
                    __float2half_rn(oacc[nf][3] * il1));
        *(uint32_t*)(Oh + o0 + col) = *(uint32_t*)&hv0;
        *(uint32_t*)(Oh + o1 + col) = *(uint32_t*)&hv1;
    }
}

// ---------------------------------------------------------------------------
extern "C" void kernel_launch(void* const* d_in, const int* in_sizes, int n_in,
                              void* d_out, int out_size) {
    const float* x  = (const float*)d_in[0];
    const float* Wq = (const float*)d_in[1];
    const float* Wk = (const float*)d_in[2];
    const float* Wv = (const float*)d_in[3];
    const float* Wo = (const float*)d_in[4];
    const int* pos  = (const int*)d_in[5];

    __half *pxf, *pWh, *pQ, *pK, *pV, *pah;
    cudaGetSymbolAddress((void**)&pxf, g_xf);
    cudaGetSymbolAddress((void**)&pWh, g_Wh);
    cudaGetSymbolAddress((void**)&pQ, g_Q);
    cudaGetSymbolAddress((void**)&pK, g_K);
    cudaGetSymbolAddress((void**)&pV, g_V);
    cudaGetSymbolAddress((void**)&pah, g_ah);

    cudaFuncSetAttribute((const void*)gemm_qkv_kernel,
                         cudaFuncAttributeMaxDynamicSharedMemorySize, GEMM_SMEM);
    cudaFuncSetAttribute((const void*)gemm_out_kernel,
                         cudaFuncAttributeMaxDynamicSharedMemorySize, OUT_SMEM);
    cudaFuncSetAttribute((const void*)attn_tc_kernel,
                         cudaFuncAttributeMaxDynamicSharedMemorySize, ATTN_SMEM);

    rope_tab_kernel<<<(Sn * 32 + 255) / 256, 256>>>(pos);
    convert_x_kernel<<<Mn * Dn / 1024, 256>>>(x, pxf);
    transpose_half_kernel<<<dim3(32, 32, 4), dim3(32, 8)>>>(Wq, Wk, Wv, Wo, pWh);

    dim3 gqkv(3 * Dn / TN, Mn / TM);  // (24, 64)
    gemm_qkv_kernel<<<gqkv, 256, GEMM_SMEM>>>(pxf, pWh, pQ, pK, pV);

    dim3 agrid(Sn / 128, Bn * Hn);  // (16, 64)
    attn_tc_kernel<<<agrid, 256, ATTN_SMEM>>>(pQ, pK, pV, pah);

    dim3 gout(Dn / TNO, Mn / TM);  // (16, 64)
    gemm_out_kernel<<<gout, 256, OUT_SMEM>>>(pah, pWh + 3 * (size_t)Dn * Dn,
                                             (float*)d_out);
}